// round 1
// baseline (speedup 1.0000x reference)
#include <cuda_runtime.h>
#include <cuda_bf16.h>

// CPDecoding: out[n] = sum_c prod_d lerp(line_coef[d][c], pos_d(n))
// coords stacked (z,y,x): table dim d uses input column (2-d).
//
// Design: SMEM diff-table tab[d][i][c] = (f0, f1-f0) as float2, row padded to
// 25 float2 (50 words) for bank-phase spreading. Warp-cooperative: 4 points
// per warp, 8 lanes per point, 3 components per lane -> conflict-free within
// a point, ~1.3x expected inter-point phase collisions. One FFMA per lerp.

#define NCOMP 24
#define RES   256
#define ROWF2 25          // float2 per row (24 data + 1 pad)
#define TAB_F2 (3 * RES * ROWF2)   // 19200 float2 = 153600 B

__global__ __launch_bounds__(1024, 1)
void cp_decode_kernel(const float* __restrict__ pts,
                      const float* __restrict__ coef,
                      float* __restrict__ out,
                      int npts)
{
    extern __shared__ float2 tab[];

    // ---- Build diff table: tab[(d*256+i)*25 + c] = (f[i], f[i+1]-f[i]) ----
    const int tid = threadIdx.x;
    for (int e = tid; e < 3 * RES * NCOMP; e += blockDim.x) {
        int d = e / (RES * NCOMP);
        int r = e - d * (RES * NCOMP);
        int i = r / NCOMP;
        int c = r - i * NCOMP;
        const float* src = coef + d * (NCOMP * RES) + c * RES;
        float f0 = __ldg(src + i);
        float f1 = (i < RES - 1) ? __ldg(src + i + 1) : f0;
        tab[(d * RES + i) * ROWF2 + c] = make_float2(f0, f1 - f0);
    }
    __syncthreads();

    const int lane = tid & 31;
    const int gwarp = (blockIdx.x * blockDim.x + tid) >> 5;
    const int nwarps = (gridDim.x * blockDim.x) >> 5;

    const int p = lane >> 3;        // point within group of 4
    const int sub = lane & 7;       // lane within point
    const int c0 = sub * 3;         // 3 components per lane

    const int niters = (npts + 3) >> 2;

    for (int iter = gwarp; iter < niters; iter += nwarps) {
        const int p0 = iter << 2;   // first point of this group

        // Stage 12 coords (4 points x 3) on lanes 0..11, broadcast via shfl.
        float v = 0.0f;
        {
            int fl = p0 * 3 + lane;
            if (lane < 12 && fl < npts * 3) v = pts[fl];
        }

        float L[3][3];
        #pragma unroll
        for (int d = 0; d < 3; d++) {
            // dim d samples input column (2-d)
            float x = __shfl_sync(0xffffffffu, v, p * 3 + (2 - d));
            float pos = fmaf(x, 127.5f, 127.5f);     // (x+1)*0.5*(R-1)
            float fp = floorf(pos);
            float w = pos - fp;
            int i = (int)fp;
            i = min(max(i, 0), RES - 1);
            const float2* row = tab + (d * RES + i) * ROWF2 + c0;
            #pragma unroll
            for (int k = 0; k < 3; k++) {
                float2 a = row[k];
                L[d][k] = fmaf(w, a.y, a.x);         // f0 + w*(f1-f0)
            }
        }

        float acc = 0.0f;
        #pragma unroll
        for (int k = 0; k < 3; k++)
            acc = fmaf(L[0][k] * L[1][k], L[2][k], acc);

        // Reduce the 8 lanes of this point (sub 0..7 -> xor 4,2,1).
        acc += __shfl_xor_sync(0xffffffffu, acc, 4);
        acc += __shfl_xor_sync(0xffffffffu, acc, 2);
        acc += __shfl_xor_sync(0xffffffffu, acc, 1);

        int pw = p0 + p;
        if (sub == 0 && pw < npts)
            out[pw] = acc;
    }
}

extern "C" void kernel_launch(void* const* d_in, const int* in_sizes, int n_in,
                              void* d_out, int out_size)
{
    const float* pts  = (const float*)d_in[0];   // [N,3] float32
    const float* coef = (const float*)d_in[1];   // [3,24,256] float32
    float* out = (float*)d_out;

    const int npts = in_sizes[0] / 3;
    const size_t smem = TAB_F2 * sizeof(float2); // 153600 B

    static bool attr_set = false;
    // (idempotent host-side attribute; not a stream op, safe under capture)
    cudaFuncSetAttribute(cp_decode_kernel,
                         cudaFuncAttributeMaxDynamicSharedMemorySize,
                         (int)smem);
    (void)attr_set;

    cp_decode_kernel<<<148, 1024, smem>>>(pts, coef, out, npts);
}

// round 2
// speedup vs baseline: 1.1610x; 1.1610x over previous
#include <cuda_runtime.h>
#include <cuda_bf16.h>

// CPDecoding: out[n] = sum_c prod_d lerp(line_coef[d][c], pos_d(n))
// coords stacked (z,y,x): table dim d uses input column (2-d).
//
// R2 design: SMEM table of float4 = (f0_{2j}, d_{2j}, f0_{2j+1}, d_{2j+1}),
// 12 float4 per row (192 B stride, no pad). Warp = 4 points x 8 lanes.
// LDS.128 with all 8 lanes of a phase reading 8 CONSECUTIVE float4 of ONE
// row -> 8 distinct quad-banks regardless of row base -> conflict-free by
// construction (the R1 kernel paired two random rows per phase -> ~2x).
// Per point-dim: 2 LDS.128 phases (k0: float4 0-7, k1: float4 8-11 + masked).

#define NCOMP 24
#define RES   256
#define ROWF4 12                        // float4 per row
#define TAB_F4 (3 * RES * ROWF4 + 4)    // +4 tail pad for k1 overread
// bytes = 9220 * 16 = 147520

__global__ __launch_bounds__(1024, 1)
void cp_decode_kernel(const float* __restrict__ pts,
                      const float* __restrict__ coef,
                      float* __restrict__ out,
                      int npts)
{
    extern __shared__ float4 tab[];

    // ---- Build: tab[(d*256+i)*12 + j] = (f0[2j], f1-f0[2j], f0[2j+1], ...) ----
    const int tid = threadIdx.x;
    for (int e = tid; e < 3 * RES * ROWF4; e += blockDim.x) {
        int d   = e / (RES * ROWF4);
        int rem = e - d * (RES * ROWF4);
        int i   = rem / ROWF4;
        int j   = rem - i * ROWF4;
        const float* src = coef + d * (NCOMP * RES);
        const float* ca = src + (2 * j) * RES;
        const float* cb = src + (2 * j + 1) * RES;
        float a0 = __ldg(ca + i);
        float a1 = (i < RES - 1) ? __ldg(ca + i + 1) : a0;
        float b0 = __ldg(cb + i);
        float b1 = (i < RES - 1) ? __ldg(cb + i + 1) : b0;
        tab[e] = make_float4(a0, a1 - a0, b0, b1 - b0);
    }
    // tail pad (read by masked lanes of the last row)
    if (tid < 4) tab[3 * RES * ROWF4 + tid] = make_float4(0.f, 0.f, 0.f, 0.f);
    __syncthreads();

    const int lane   = tid & 31;
    const int gwarp  = (blockIdx.x * blockDim.x + tid) >> 5;
    const int nwarps = (gridDim.x * blockDim.x) >> 5;

    const int p   = lane >> 3;       // point slot within group of 4
    const int sub = lane & 7;        // lane within point
    const float kmask = (sub < 4) ? 1.0f : 0.0f;   // k1 validity

    const int niters = (npts + 3) >> 2;

    for (int iter = gwarp; iter < niters; iter += nwarps) {
        const int p0 = iter << 2;

        // Stage 12 coords (4 points x 3) on lanes 0..11, broadcast via shfl.
        float v = 0.0f;
        {
            int fl = p0 * 3 + lane;
            if (lane < 12 && fl < npts * 3) v = pts[fl];
        }

        // Per dim: lerp 4 component-pairs (2 from k0 phase, 2 from k1 phase).
        float L0[3], L1[3], M0[3], M1[3];
        #pragma unroll
        for (int d = 0; d < 3; d++) {
            float x   = __shfl_sync(0xffffffffu, v, p * 3 + (2 - d));
            float pos = fmaf(x, 127.5f, 127.5f);    // (x+1)*0.5*(R-1)
            float fp  = floorf(pos);
            float w   = pos - fp;
            int   i   = (int)fp;
            i = min(max(i, 0), RES - 1);
            const float4* row = tab + (d * RES + i) * ROWF4;
            float4 A = row[sub];          // comps 2sub, 2sub+1   (phase: f4 0-7)
            float4 B = row[8 + sub];      // comps 16+2sub,17+2sub (phase: f4 8-15)
            L0[d] = fmaf(w, A.y, A.x);
            L1[d] = fmaf(w, A.w, A.z);
            M0[d] = fmaf(w, B.y, B.x);
            M1[d] = fmaf(w, B.w, B.z);
        }

        float acc = fmaf(L1[0] * L1[1], L1[2], L0[0] * L0[1] * L0[2]);
        float accm = fmaf(M1[0] * M1[1], M1[2], M0[0] * M0[1] * M0[2]);
        acc = fmaf(kmask, accm, acc);    // lanes 4-7 read garbage in B: masked

        // Reduce the 8 lanes of this point.
        acc += __shfl_xor_sync(0xffffffffu, acc, 4);
        acc += __shfl_xor_sync(0xffffffffu, acc, 2);
        acc += __shfl_xor_sync(0xffffffffu, acc, 1);

        int pw = p0 + p;
        if (sub == 0 && pw < npts)
            out[pw] = acc;
    }
}

extern "C" void kernel_launch(void* const* d_in, const int* in_sizes, int n_in,
                              void* d_out, int out_size)
{
    const float* pts  = (const float*)d_in[0];   // [N,3] float32
    const float* coef = (const float*)d_in[1];   // [3,24,256] float32
    float* out = (float*)d_out;

    const int npts = in_sizes[0] / 3;
    const size_t smem = TAB_F4 * sizeof(float4); // 147520 B

    cudaFuncSetAttribute(cp_decode_kernel,
                         cudaFuncAttributeMaxDynamicSharedMemorySize,
                         (int)smem);

    cp_decode_kernel<<<148, 1024, smem>>>(pts, coef, out, npts);
}

// round 3
// speedup vs baseline: 1.3892x; 1.1966x over previous
#include <cuda_runtime.h>
#include <cuda_bf16.h>

// CPDecoding: out[n] = sum_c prod_d lerp(line_coef[d][c], pos_d(n))
// coords stacked (z,y,x): table dim d uses input column (2-d).
//
// R3: same conflict-free float4 diff-table as R2 (8 consecutive float4 of ONE
// row per LDS.128 phase -> distinct quad-banks for any row). New: 8 points
// per warp-iter (two independent 4-pt groups -> 2x ILP) and software-
// pipelined coordinate loads (next iter's 24 coords LDG'd during current
// body), removing the ~600-cyc global load from the dependent chain.

#define NCOMP 24
#define RES   256
#define ROWF4 12                        // float4 per row (192 B)
#define TAB_F4 (3 * RES * ROWF4 + 4)    // +4 tail pad for masked overread

__global__ __launch_bounds__(1024, 1)
void cp_decode_kernel(const float* __restrict__ pts,
                      const float* __restrict__ coef,
                      float* __restrict__ out,
                      int npts)
{
    extern __shared__ float4 tab[];

    // ---- Build diff table: tab[(d*256+i)*12+j] = (f0,d)_{2j},(f0,d)_{2j+1} ----
    const int tid = threadIdx.x;
    for (int e = tid; e < 3 * RES * ROWF4; e += blockDim.x) {
        int d   = e / (RES * ROWF4);
        int rem = e - d * (RES * ROWF4);
        int i   = rem / ROWF4;
        int j   = rem - i * ROWF4;
        const float* src = coef + d * (NCOMP * RES);
        const float* ca = src + (2 * j) * RES;
        const float* cb = src + (2 * j + 1) * RES;
        float a0 = __ldg(ca + i);
        float a1 = (i < RES - 1) ? __ldg(ca + i + 1) : a0;
        float b0 = __ldg(cb + i);
        float b1 = (i < RES - 1) ? __ldg(cb + i + 1) : b0;
        tab[e] = make_float4(a0, a1 - a0, b0, b1 - b0);
    }
    if (tid < 4) tab[3 * RES * ROWF4 + tid] = make_float4(0.f, 0.f, 0.f, 0.f);
    __syncthreads();

    const int lane   = tid & 31;
    const int gwarp  = (blockIdx.x * blockDim.x + tid) >> 5;
    const int nwarps = (gridDim.x * blockDim.x) >> 5;

    const int p   = lane >> 3;                     // point slot in group
    const int sub = lane & 7;                      // lane within point
    const float kmask = (sub < 4) ? 1.0f : 0.0f;   // B-phase validity

    const int niters = (npts + 7) >> 3;            // 8 points per iter

    // Prologue: stage coords for first iteration (lanes 0..23 hold 8x3 floats)
    int iter = gwarp;
    float v = 0.0f;
    if (iter < niters) {
        int fl = iter * 24 + lane;
        if (lane < 24 && fl < npts * 3) v = __ldg(pts + fl);
    }

    for (; iter < niters; iter += nwarps) {
        const int base = iter << 3;

        // Extract this lane's two points' coords from the staged register.
        float xA[3], xB[3];
        #pragma unroll
        for (int d = 0; d < 3; d++) {
            xA[d] = __shfl_sync(0xffffffffu, v, p * 3 + (2 - d));
            xB[d] = __shfl_sync(0xffffffffu, v, 12 + p * 3 + (2 - d));
        }

        // Prefetch next iteration's coords (latency hidden under body).
        float vn = 0.0f;
        {
            int itn = iter + nwarps;
            int fl = itn * 24 + lane;
            if (itn < niters && lane < 24 && fl < npts * 3)
                vn = __ldg(pts + fl);
        }

        float accA, accB;
        // ---- group A: points base..base+3 ----
        {
            float L0[3], L1[3], M0[3], M1[3];
            #pragma unroll
            for (int d = 0; d < 3; d++) {
                float pos = fmaf(xA[d], 127.5f, 127.5f);
                float fp  = floorf(pos);
                float w   = pos - fp;
                int   i   = min(max((int)fp, 0), RES - 1);
                const float4* row = tab + (d * RES + i) * ROWF4;
                float4 Aq = row[sub];
                float4 Bq = row[8 + sub];
                L0[d] = fmaf(w, Aq.y, Aq.x);
                L1[d] = fmaf(w, Aq.w, Aq.z);
                M0[d] = fmaf(w, Bq.y, Bq.x);
                M1[d] = fmaf(w, Bq.w, Bq.z);
            }
            float a = fmaf(L1[0] * L1[1], L1[2], L0[0] * L0[1] * L0[2]);
            float m = fmaf(M1[0] * M1[1], M1[2], M0[0] * M0[1] * M0[2]);
            accA = fmaf(kmask, m, a);
        }
        // ---- group B: points base+4..base+7 ----
        {
            float L0[3], L1[3], M0[3], M1[3];
            #pragma unroll
            for (int d = 0; d < 3; d++) {
                float pos = fmaf(xB[d], 127.5f, 127.5f);
                float fp  = floorf(pos);
                float w   = pos - fp;
                int   i   = min(max((int)fp, 0), RES - 1);
                const float4* row = tab + (d * RES + i) * ROWF4;
                float4 Aq = row[sub];
                float4 Bq = row[8 + sub];
                L0[d] = fmaf(w, Aq.y, Aq.x);
                L1[d] = fmaf(w, Aq.w, Aq.z);
                M0[d] = fmaf(w, Bq.y, Bq.x);
                M1[d] = fmaf(w, Bq.w, Bq.z);
            }
            float a = fmaf(L1[0] * L1[1], L1[2], L0[0] * L0[1] * L0[2]);
            float m = fmaf(M1[0] * M1[1], M1[2], M0[0] * M0[1] * M0[2]);
            accB = fmaf(kmask, m, a);
        }

        // Two independent 8-lane reductions, interleaved.
        #pragma unroll
        for (int s = 4; s; s >>= 1) {
            accA += __shfl_xor_sync(0xffffffffu, accA, s);
            accB += __shfl_xor_sync(0xffffffffu, accB, s);
        }

        if (sub == 0) {
            int pA = base + p;
            int pB = base + 4 + p;
            if (pA < npts) out[pA] = accA;
            if (pB < npts) out[pB] = accB;
        }

        v = vn;
    }
}

extern "C" void kernel_launch(void* const* d_in, const int* in_sizes, int n_in,
                              void* d_out, int out_size)
{
    const float* pts  = (const float*)d_in[0];   // [N,3] float32
    const float* coef = (const float*)d_in[1];   // [3,24,256] float32
    float* out = (float*)d_out;

    const int npts = in_sizes[0] / 3;
    const size_t smem = TAB_F4 * sizeof(float4); // 147520 B

    cudaFuncSetAttribute(cp_decode_kernel,
                         cudaFuncAttributeMaxDynamicSharedMemorySize,
                         (int)smem);

    cp_decode_kernel<<<148, 1024, smem>>>(pts, coef, out, npts);
}